// round 1
// baseline (speedup 1.0000x reference)
#include <cuda_runtime.h>
#include <cuda_bf16.h>
#include <math_constants.h>

// Problem constants
#define BB 2
#define SS 2048
#define DD 1024
#define HH 16
#define DK 64
#define FF 4096
#define MR (BB*SS)          // 4096 rows

// ---------------- scratch (static device globals: alloc-free rule) ----------
__device__ float g_nX [MR*DD];
__device__ float g_q  [MR*DD];
__device__ float g_k  [MR*DD];
__device__ float g_v  [MR*DD];
__device__ float g_ctx[MR*DD];
__device__ float g_X1 [MR*DD];
__device__ float g_h  [(size_t)MR*FF];

// ---------------- LayerNorm: one block per row, D=1024 ----------------------
__global__ __launch_bounds__(256)
void ln_kernel(const float* __restrict__ X, const float* __restrict__ g,
               const float* __restrict__ b, float* __restrict__ Y)
{
    const int row = blockIdx.x;
    const int tid = threadIdx.x;
    const float4 x = ((const float4*)(X + (size_t)row * DD))[tid];

    float s  = x.x + x.y + x.z + x.w;
    float ss = x.x*x.x + x.y*x.y + x.z*x.z + x.w*x.w;
    #pragma unroll
    for (int o = 16; o; o >>= 1) {
        s  += __shfl_xor_sync(0xffffffffu, s,  o);
        ss += __shfl_xor_sync(0xffffffffu, ss, o);
    }
    __shared__ float sw[8], sw2[8];
    const int w = tid >> 5, ln = tid & 31;
    if (ln == 0) { sw[w] = s; sw2[w] = ss; }
    __syncthreads();
    float tot = 0.f, tot2 = 0.f;
    #pragma unroll
    for (int i = 0; i < 8; i++) { tot += sw[i]; tot2 += sw2[i]; }

    const float mean = tot * (1.0f / DD);
    const float var  = tot2 * (1.0f / DD) - mean * mean;
    const float rstd = rsqrtf(var + 1e-5f);

    const float4 gv = ((const float4*)g)[tid];
    const float4 bv = ((const float4*)b)[tid];
    float4 y;
    y.x = (x.x - mean) * rstd * gv.x + bv.x;
    y.y = (x.y - mean) * rstd * gv.y + bv.y;
    y.z = (x.z - mean) * rstd * gv.z + bv.z;
    y.w = (x.w - mean) * rstd * gv.w + bv.w;
    ((float4*)(Y + (size_t)row * DD))[tid] = y;
}

// ---------------- SGEMM 128x128x16, 256 thr, 8x8 microtile ------------------
// mode bits: 1 = +bias[n], 2 = +resid[m*N+n], 4 = relu
__global__ __launch_bounds__(256, 2)
void sgemm_kernel(const float* __restrict__ A, const float* __restrict__ B,
                  float* __restrict__ C, int M, int N, int K,
                  const float* __restrict__ bias, const float* __restrict__ resid,
                  int mode)
{
    __shared__ float As[16][128];   // transposed A tile: As[k][m]
    __shared__ float Bs[16][128];   // Bs[k][n]

    const int tid = threadIdx.x;
    const int tx = tid & 15, ty = tid >> 4;
    const int m0 = blockIdx.y * 128;
    const int n0 = blockIdx.x * 128;

    float acc[8][8];
    #pragma unroll
    for (int i = 0; i < 8; i++)
        #pragma unroll
        for (int j = 0; j < 8; j++) acc[i][j] = 0.f;

    for (int k0 = 0; k0 < K; k0 += 16) {
        #pragma unroll
        for (int l = 0; l < 2; l++) {
            const int idx = tid + l * 256;              // 0..511
            // A tile: 128 rows x 4 float4 along K
            const int ar = idx >> 2, ac = (idx & 3) << 2;
            float4 a = *(const float4*)(A + (size_t)(m0 + ar) * K + k0 + ac);
            As[ac + 0][ar] = a.x; As[ac + 1][ar] = a.y;
            As[ac + 2][ar] = a.z; As[ac + 3][ar] = a.w;
            // B tile: 16 rows x 32 float4 along N
            const int br = idx >> 5, bc = (idx & 31) << 2;
            float4 b = *(const float4*)(B + (size_t)(k0 + br) * N + n0 + bc);
            *(float4*)&Bs[br][bc] = b;
        }
        __syncthreads();

        #pragma unroll
        for (int kk = 0; kk < 16; kk++) {
            float a[8], b[8];
            *(float4*)(a)     = *(const float4*)&As[kk][ty * 8];
            *(float4*)(a + 4) = *(const float4*)&As[kk][ty * 8 + 4];
            *(float4*)(b)     = *(const float4*)&Bs[kk][tx * 8];
            *(float4*)(b + 4) = *(const float4*)&Bs[kk][tx * 8 + 4];
            #pragma unroll
            for (int i = 0; i < 8; i++)
                #pragma unroll
                for (int j = 0; j < 8; j++)
                    acc[i][j] = fmaf(a[i], b[j], acc[i][j]);
        }
        __syncthreads();
    }

    // epilogue
    #pragma unroll
    for (int i = 0; i < 8; i++) {
        const int m = m0 + ty * 8 + i;
        #pragma unroll
        for (int j4 = 0; j4 < 2; j4++) {
            const int n = n0 + tx * 8 + j4 * 4;
            float4 v;
            v.x = acc[i][j4 * 4 + 0];
            v.y = acc[i][j4 * 4 + 1];
            v.z = acc[i][j4 * 4 + 2];
            v.w = acc[i][j4 * 4 + 3];
            if (mode & 1) {
                float4 bb = *(const float4*)(bias + n);
                v.x += bb.x; v.y += bb.y; v.z += bb.z; v.w += bb.w;
            }
            if (mode & 2) {
                float4 rr = *(const float4*)(resid + (size_t)m * N + n);
                v.x += rr.x; v.y += rr.y; v.z += rr.z; v.w += rr.w;
            }
            if (mode & 4) {
                v.x = fmaxf(v.x, 0.f); v.y = fmaxf(v.y, 0.f);
                v.z = fmaxf(v.z, 0.f); v.w = fmaxf(v.w, 0.f);
            }
            *(float4*)(C + (size_t)m * N + n) = v;
        }
    }
}

// ---------------- Flash attention: 64q x 64k tiles, DK=64 -------------------
#define AST 65   // smem row stride (anti bank-conflict)

__global__ __launch_bounds__(256)
void attn_kernel(const float* __restrict__ Qg, const float* __restrict__ Kg,
                 const float* __restrict__ Vg, float* __restrict__ Og)
{
    extern __shared__ float smp[];
    float* Qs = smp;                 // [64][AST]
    float* KP = smp + 64 * AST;      // K tile, then reused as P tile
    float* Vs = smp + 2 * 64 * AST;  // [64][AST]

    const int tid = threadIdx.x;
    const int tx = tid & 15, ty = tid >> 4;
    const int qt = blockIdx.x;       // query tile (0..31)
    const int bh = blockIdx.y;       // b*H+h (0..31)
    const int b  = bh >> 4, h = bh & 15;
    const size_t base = (size_t)b * SS * DD + (size_t)h * DK;
    const int q0 = qt * 64;

    // load Q tile (scaled by 1/sqrt(DK))
    #pragma unroll
    for (int l = 0; l < 4; l++) {
        const int idx = tid + l * 256;            // 0..1023
        const int r = idx >> 4, c = (idx & 15) << 2;
        float4 qv = *(const float4*)(Qg + base + (size_t)(q0 + r) * DD + c);
        float* dst = &Qs[r * AST + c];
        dst[0] = qv.x * 0.125f; dst[1] = qv.y * 0.125f;
        dst[2] = qv.z * 0.125f; dst[3] = qv.w * 0.125f;
    }

    float m_i[4], l_i[4], o[4][4];
    #pragma unroll
    for (int i = 0; i < 4; i++) {
        m_i[i] = -CUDART_INF_F; l_i[i] = 0.f;
        #pragma unroll
        for (int j = 0; j < 4; j++) o[i][j] = 0.f;
    }

    for (int kt = 0; kt < SS / 64; kt++) {
        __syncthreads();   // prior PV done reading KP/Vs (also covers Q load on iter 0)
        const int kb = kt * 64;
        #pragma unroll
        for (int l = 0; l < 4; l++) {
            const int idx = tid + l * 256;
            const int r = idx >> 4, c = (idx & 15) << 2;
            float4 kv = *(const float4*)(Kg + base + (size_t)(kb + r) * DD + c);
            float* kd = &KP[r * AST + c];
            kd[0] = kv.x; kd[1] = kv.y; kd[2] = kv.z; kd[3] = kv.w;
            float4 vv = *(const float4*)(Vg + base + (size_t)(kb + r) * DD + c);
            float* vd = &Vs[r * AST + c];
            vd[0] = vv.x; vd[1] = vv.y; vd[2] = vv.z; vd[3] = vv.w;
        }
        __syncthreads();

        // S = (Q*scale) @ K^T  -> 4x4 per thread
        float s[4][4];
        #pragma unroll
        for (int i = 0; i < 4; i++)
            #pragma unroll
            for (int j = 0; j < 4; j++) s[i][j] = 0.f;

        #pragma unroll 8
        for (int d = 0; d < 64; d++) {
            float a[4], bb[4];
            #pragma unroll
            for (int i = 0; i < 4; i++) a[i]  = Qs[(ty * 4 + i) * AST + d];
            #pragma unroll
            for (int j = 0; j < 4; j++) bb[j] = KP[(tx * 4 + j) * AST + d];
            #pragma unroll
            for (int i = 0; i < 4; i++)
                #pragma unroll
                for (int j = 0; j < 4; j++)
                    s[i][j] = fmaf(a[i], bb[j], s[i][j]);
        }
        __syncthreads();   // all threads done reading K before P overwrites it

        // online softmax (row groups = 16 lanes sharing ty)
        #pragma unroll
        for (int i = 0; i < 4; i++) {
            float mx = fmaxf(fmaxf(s[i][0], s[i][1]), fmaxf(s[i][2], s[i][3]));
            #pragma unroll
            for (int off = 8; off; off >>= 1)
                mx = fmaxf(mx, __shfl_xor_sync(0xffffffffu, mx, off, 16));
            const float mn   = fmaxf(m_i[i], mx);
            const float corr = __expf(m_i[i] - mn);
            m_i[i] = mn;
            float sum = 0.f;
            #pragma unroll
            for (int j = 0; j < 4; j++) {
                float p = __expf(s[i][j] - mn);
                s[i][j] = p; sum += p;
            }
            #pragma unroll
            for (int off = 8; off; off >>= 1)
                sum += __shfl_xor_sync(0xffffffffu, sum, off, 16);
            l_i[i] = l_i[i] * corr + sum;
            #pragma unroll
            for (int j = 0; j < 4; j++) o[i][j] *= corr;
            #pragma unroll
            for (int j = 0; j < 4; j++)
                KP[(ty * 4 + i) * AST + tx * 4 + j] = s[i][j];
        }
        __syncthreads();

        // O += P @ V
        #pragma unroll 8
        for (int kq = 0; kq < 64; kq++) {
            float a[4], bb[4];
            #pragma unroll
            for (int i = 0; i < 4; i++) a[i]  = KP[(ty * 4 + i) * AST + kq];
            #pragma unroll
            for (int j = 0; j < 4; j++) bb[j] = Vs[kq * AST + tx * 4 + j];
            #pragma unroll
            for (int i = 0; i < 4; i++)
                #pragma unroll
                for (int j = 0; j < 4; j++)
                    o[i][j] = fmaf(a[i], bb[j], o[i][j]);
        }
    }

    // normalize + store ctx in [B,S,D] layout
    #pragma unroll
    for (int i = 0; i < 4; i++) {
        const float inv = 1.0f / l_i[i];
        float4 ov;
        ov.x = o[i][0] * inv; ov.y = o[i][1] * inv;
        ov.z = o[i][2] * inv; ov.w = o[i][3] * inv;
        *(float4*)(Og + base + (size_t)(q0 + ty * 4 + i) * DD + tx * 4) = ov;
    }
}

// ---------------- launch -----------------------------------------------------
extern "C" void kernel_launch(void* const* d_in, const int* in_sizes, int n_in,
                              void* d_out, int out_size)
{
    const float* X   = (const float*)d_in[0];
    const float* Wq  = (const float*)d_in[1];
    const float* Wk  = (const float*)d_in[2];
    const float* Wv  = (const float*)d_in[3];
    const float* Wo  = (const float*)d_in[4];
    const float* W1  = (const float*)d_in[5];
    const float* b1  = (const float*)d_in[6];
    const float* W2  = (const float*)d_in[7];
    const float* b2  = (const float*)d_in[8];
    const float* g1  = (const float*)d_in[9];
    const float* be1 = (const float*)d_in[10];
    const float* g2  = (const float*)d_in[11];
    const float* be2 = (const float*)d_in[12];
    float* out = (float*)d_out;

    float *nX, *q, *k, *v, *ctx, *X1, *hbuf;
    cudaGetSymbolAddress((void**)&nX,   g_nX);
    cudaGetSymbolAddress((void**)&q,    g_q);
    cudaGetSymbolAddress((void**)&k,    g_k);
    cudaGetSymbolAddress((void**)&v,    g_v);
    cudaGetSymbolAddress((void**)&ctx,  g_ctx);
    cudaGetSymbolAddress((void**)&X1,   g_X1);
    cudaGetSymbolAddress((void**)&hbuf, g_h);

    const size_t attn_smem = (size_t)3 * 64 * AST * sizeof(float);   // ~49.9 KB
    cudaFuncSetAttribute(attn_kernel, cudaFuncAttributeMaxDynamicSharedMemorySize,
                         (int)attn_smem);

    dim3 thr(256);

    // 1. LN1
    ln_kernel<<<MR, thr>>>(X, g1, be1, nX);

    // 2-4. Q, K, V projections
    dim3 gQKV(DD / 128, MR / 128);
    sgemm_kernel<<<gQKV, thr>>>(nX, Wq, q, MR, DD, DD, nullptr, nullptr, 0);
    sgemm_kernel<<<gQKV, thr>>>(nX, Wk, k, MR, DD, DD, nullptr, nullptr, 0);
    sgemm_kernel<<<gQKV, thr>>>(nX, Wv, v, MR, DD, DD, nullptr, nullptr, 0);

    // 5. attention
    attn_kernel<<<dim3(SS / 64, BB * HH), thr, attn_smem>>>(q, k, v, ctx);

    // 6. output projection + residual: X1 = X + ctx @ Wo
    sgemm_kernel<<<gQKV, thr>>>(ctx, Wo, X1, MR, DD, DD, nullptr, X, 2);

    // 7. LN2
    ln_kernel<<<MR, thr>>>(X1, g2, be2, nX);

    // 8. FFN up: h = relu(nX @ W1 + b1)
    sgemm_kernel<<<dim3(FF / 128, MR / 128), thr>>>(nX, W1, hbuf, MR, FF, DD,
                                                    b1, nullptr, 1 | 4);

    // 9. FFN down + residual: out = X1 + h @ W2 + b2
    sgemm_kernel<<<dim3(DD / 128, MR / 128), thr>>>(hbuf, W2, out, MR, DD, FF,
                                                    b2, X1, 1 | 2);
}

// round 3
// speedup vs baseline: 1.9368x; 1.9368x over previous
#include <cuda_runtime.h>
#include <cuda_bf16.h>
#include <math_constants.h>
#include <cstdint>

// Problem constants
#define BB 2
#define SS 2048
#define DD 1024
#define HH 16
#define DK 64
#define FF 4096
#define MR (BB*SS)          // 4096 rows

// ---------------- scratch (static device globals: alloc-free rule) ----------
__device__ float g_nX [MR*DD];
__device__ float g_q  [MR*DD];
__device__ float g_k  [MR*DD];
__device__ float g_v  [MR*DD];
__device__ float g_ctx[MR*DD];
__device__ float g_X1 [MR*DD];
__device__ float g_h  [(size_t)MR*FF];
__device__ float g_WqT[DD*DD];
__device__ float g_WkT[DD*DD];
__device__ float g_WvT[DD*DD];
__device__ float g_WoT[DD*DD];
__device__ float g_W1T[(size_t)DD*FF];
__device__ float g_W2T[(size_t)DD*FF];

// ---------------- small helpers ---------------------------------------------
__device__ __forceinline__ uint32_t smem_u32(const void* p) {
    uint32_t a;
    asm("{ .reg .u64 t; cvta.to.shared.u64 t, %1; cvt.u32.u64 %0, t; }"
        : "=r"(a) : "l"(p));
    return a;
}
__device__ __forceinline__ float rna_tf32(float x) {
    uint32_t u;
    asm("cvt.rna.tf32.f32 %0, %1;" : "=r"(u) : "f"(x));
    return __uint_as_float(u);
}
__device__ __forceinline__ void cp16(uint32_t s, const void* g) {
    asm volatile("cp.async.cg.shared.global [%0], [%1], 16;" :: "r"(s), "l"(g));
}
__device__ __forceinline__ void mma_tf32(float* c, const uint32_t* a,
                                         const uint32_t* b) {
    asm volatile(
        "mma.sync.aligned.m16n8k8.row.col.f32.tf32.tf32.f32 "
        "{%0,%1,%2,%3}, {%4,%5,%6,%7}, {%8,%9}, {%0,%1,%2,%3};"
        : "+f"(c[0]), "+f"(c[1]), "+f"(c[2]), "+f"(c[3])
        : "r"(a[0]), "r"(a[1]), "r"(a[2]), "r"(a[3]),
          "r"(b[0]), "r"(b[1]));
}

// ---------------- weight transpose with tf32 round-to-nearest ---------------
// in: R x C row-major ; out: C x R row-major, out[c][r] = rna(in[r][c])
__global__ __launch_bounds__(256)
void transpose_rna_kernel(const float* __restrict__ in, float* __restrict__ out,
                          int R, int C)
{
    __shared__ float t[32][33];
    const int bx = blockIdx.x * 32, by = blockIdx.y * 32;
    const int tx = threadIdx.x & 31, ty = threadIdx.x >> 5;  // 32 x 8
    #pragma unroll
    for (int i = 0; i < 32; i += 8)
        t[ty + i][tx] = in[(size_t)(by + ty + i) * C + bx + tx];
    __syncthreads();
    #pragma unroll
    for (int i = 0; i < 32; i += 8)
        out[(size_t)(bx + ty + i) * R + by + tx] = rna_tf32(t[tx][ty + i]);
}

// ---------------- LayerNorm (rna-rounded output) -----------------------------
__global__ __launch_bounds__(256)
void ln_kernel(const float* __restrict__ X, const float* __restrict__ g,
               const float* __restrict__ b, float* __restrict__ Y)
{
    const int row = blockIdx.x;
    const int tid = threadIdx.x;
    const float4 x = ((const float4*)(X + (size_t)row * DD))[tid];

    float s  = x.x + x.y + x.z + x.w;
    float ss = x.x*x.x + x.y*x.y + x.z*x.z + x.w*x.w;
    #pragma unroll
    for (int o = 16; o; o >>= 1) {
        s  += __shfl_xor_sync(0xffffffffu, s,  o);
        ss += __shfl_xor_sync(0xffffffffu, ss, o);
    }
    __shared__ float sw[8], sw2[8];
    const int w = tid >> 5, ln = tid & 31;
    if (ln == 0) { sw[w] = s; sw2[w] = ss; }
    __syncthreads();
    float tot = 0.f, tot2 = 0.f;
    #pragma unroll
    for (int i = 0; i < 8; i++) { tot += sw[i]; tot2 += sw2[i]; }

    const float mean = tot * (1.0f / DD);
    const float var  = tot2 * (1.0f / DD) - mean * mean;
    const float rstd = rsqrtf(var + 1e-5f);

    const float4 gv = ((const float4*)g)[tid];
    const float4 bv = ((const float4*)b)[tid];
    float4 y;
    y.x = rna_tf32((x.x - mean) * rstd * gv.x + bv.x);
    y.y = rna_tf32((x.y - mean) * rstd * gv.y + bv.y);
    y.z = rna_tf32((x.z - mean) * rstd * gv.z + bv.z);
    y.w = rna_tf32((x.w - mean) * rstd * gv.w + bv.w);
    ((float4*)(Y + (size_t)row * DD))[tid] = y;
}

// ---------------- tf32 mma.sync GEMM -----------------------------------------
// C[M,N] = A[M,K] @ Bt[N,K]^T.  A row-major [M,K], Bt row-major [N,K].
// CTA tile 128x128, K tile 32, 8 warps (4x2), warp tile 32x64.
// Smem: As[m][36], Bs[n][36] (stride 36 floats -> conflict-free frag loads).
// mode bits: 1 = +bias[n], 2 = +resid[m*N+n], 4 = relu, 8 = rna-round output
#define KSTR 36
#define TILE_F (128 * KSTR)                 // floats per operand tile (4608)
#define STAGE_F (2 * TILE_F)                // A + B per stage
#define TC_SMEM (2 * STAGE_F * 4)           // 73728 bytes

__global__ __launch_bounds__(256, 2)
void tc_gemm(const float* __restrict__ A, const float* __restrict__ Bt,
             float* __restrict__ C, int M, int N, int K,
             const float* __restrict__ bias, const float* __restrict__ resid,
             int mode)
{
    extern __shared__ float smf[];
    const uint32_t sb = smem_u32(smf);

    const int tid  = threadIdx.x;
    const int wid  = tid >> 5, lane = tid & 31;
    const int tq   = lane >> 2, tr = lane & 3;
    const int wm   = (wid & 3) * 32;         // warp m offset in tile
    const int wn   = (wid >> 2) * 64;        // warp n offset in tile
    const int m0   = blockIdx.y * 128;
    const int n0   = blockIdx.x * 128;

    // global->smem load slots: idx -> row r (0..127), chunk c (0..7 float4s)
    const int nk = K / 32;

    float acc[2][8][4];
    #pragma unroll
    for (int mt = 0; mt < 2; mt++)
        #pragma unroll
        for (int nt = 0; nt < 8; nt++)
            #pragma unroll
            for (int i = 0; i < 4; i++) acc[mt][nt][i] = 0.f;

    // prologue: stage 0
    {
        const uint32_t sA = sb, sB = sb + TILE_F * 4;
        #pragma unroll
        for (int l = 0; l < 4; l++) {
            const int idx = tid + l * 256;
            const int r = idx >> 3, c = idx & 7;
            cp16(sA + (uint32_t)(r * KSTR + c * 4) * 4,
                 A + (size_t)(m0 + r) * K + c * 4);
            cp16(sB + (uint32_t)(r * KSTR + c * 4) * 4,
                 Bt + (size_t)(n0 + r) * K + c * 4);
        }
        asm volatile("cp.async.commit_group;" ::: "memory");
    }

    for (int kt = 0; kt < nk; kt++) {
        // issue next stage
        if (kt + 1 < nk) {
            const int s = (kt + 1) & 1;
            const uint32_t sA = sb + (uint32_t)s * STAGE_F * 4;
            const uint32_t sB = sA + TILE_F * 4;
            const int kof = (kt + 1) * 32;
            #pragma unroll
            for (int l = 0; l < 4; l++) {
                const int idx = tid + l * 256;
                const int r = idx >> 3, c = idx & 7;
                cp16(sA + (uint32_t)(r * KSTR + c * 4) * 4,
                     A + (size_t)(m0 + r) * K + kof + c * 4);
                cp16(sB + (uint32_t)(r * KSTR + c * 4) * 4,
                     Bt + (size_t)(n0 + r) * K + kof + c * 4);
            }
            asm volatile("cp.async.commit_group;" ::: "memory");
            asm volatile("cp.async.wait_group 1;" ::: "memory");
        } else {
            asm volatile("cp.async.wait_group 0;" ::: "memory");
        }
        __syncthreads();

        const uint32_t* Asu = (const uint32_t*)(smf + (size_t)(kt & 1) * STAGE_F);
        const uint32_t* Bsu = Asu + TILE_F;

        #pragma unroll
        for (int ks = 0; ks < 4; ks++) {
            const int kc = ks * 8 + tr;
            uint32_t a[2][4], b[8][2];
            #pragma unroll
            for (int mt = 0; mt < 2; mt++) {
                const int row = wm + mt * 16 + tq;
                a[mt][0] = Asu[row * KSTR + kc];
                a[mt][1] = Asu[(row + 8) * KSTR + kc];
                a[mt][2] = Asu[row * KSTR + kc + 4];
                a[mt][3] = Asu[(row + 8) * KSTR + kc + 4];
            }
            #pragma unroll
            for (int nt = 0; nt < 8; nt++) {
                const int col = wn + nt * 8 + tq;
                b[nt][0] = Bsu[col * KSTR + kc];
                b[nt][1] = Bsu[col * KSTR + kc + 4];
            }
            #pragma unroll
            for (int mt = 0; mt < 2; mt++)
                #pragma unroll
                for (int nt = 0; nt < 8; nt++)
                    mma_tf32(acc[mt][nt], a[mt], b[nt]);
        }
        __syncthreads();
    }

    // epilogue: each thread owns rows {r0, r0+8} x cols {2tr, 2tr+1} per subtile
    #pragma unroll
    for (int mt = 0; mt < 2; mt++) {
        const int r0 = m0 + wm + mt * 16 + tq;
        #pragma unroll
        for (int half = 0; half < 2; half++) {
            const int m = r0 + half * 8;
            #pragma unroll
            for (int nt = 0; nt < 8; nt++) {
                const int n = n0 + wn + nt * 8 + tr * 2;
                float vx = acc[mt][nt][half * 2 + 0];
                float vy = acc[mt][nt][half * 2 + 1];
                if (mode & 1) {
                    const float2 bb = *(const float2*)(bias + n);
                    vx += bb.x; vy += bb.y;
                }
                if (mode & 2) {
                    const float2 rr = *(const float2*)(resid + (size_t)m * N + n);
                    vx += rr.x; vy += rr.y;
                }
                if (mode & 4) { vx = fmaxf(vx, 0.f); vy = fmaxf(vy, 0.f); }
                if (mode & 8) { vx = rna_tf32(vx); vy = rna_tf32(vy); }
                float2 o; o.x = vx; o.y = vy;
                *(float2*)(C + (size_t)m * N + n) = o;
            }
        }
    }
}

// ---------------- Flash attention (fp32 FFMA, rna-rounded output) ------------
#define AST 65

__global__ __launch_bounds__(256)
void attn_kernel(const float* __restrict__ Qg, const float* __restrict__ Kg,
                 const float* __restrict__ Vg, float* __restrict__ Og)
{
    extern __shared__ float smp[];
    float* Qs = smp;
    float* KP = smp + 64 * AST;
    float* Vs = smp + 2 * 64 * AST;

    const int tid = threadIdx.x;
    const int tx = tid & 15, ty = tid >> 4;
    const int qt = blockIdx.x;
    const int bh = blockIdx.y;
    const int b  = bh >> 4, h = bh & 15;
    const size_t base = (size_t)b * SS * DD + (size_t)h * DK;
    const int q0 = qt * 64;

    #pragma unroll
    for (int l = 0; l < 4; l++) {
        const int idx = tid + l * 256;
        const int r = idx >> 4, c = (idx & 15) << 2;
        float4 qv = *(const float4*)(Qg + base + (size_t)(q0 + r) * DD + c);
        float* dst = &Qs[r * AST + c];
        dst[0] = qv.x * 0.125f; dst[1] = qv.y * 0.125f;
        dst[2] = qv.z * 0.125f; dst[3] = qv.w * 0.125f;
    }

    float m_i[4], l_i[4], o[4][4];
    #pragma unroll
    for (int i = 0; i < 4; i++) {
        m_i[i] = -CUDART_INF_F; l_i[i] = 0.f;
        #pragma unroll
        for (int j = 0; j < 4; j++) o[i][j] = 0.f;
    }

    for (int kt = 0; kt < SS / 64; kt++) {
        __syncthreads();
        const int kb = kt * 64;
        #pragma unroll
        for (int l = 0; l < 4; l++) {
            const int idx = tid + l * 256;
            const int r = idx >> 4, c = (idx & 15) << 2;
            float4 kv = *(const float4*)(Kg + base + (size_t)(kb + r) * DD + c);
            float* kd = &KP[r * AST + c];
            kd[0] = kv.x; kd[1] = kv.y; kd[2] = kv.z; kd[3] = kv.w;
            float4 vv = *(const float4*)(Vg + base + (size_t)(kb + r) * DD + c);
            float* vd = &Vs[r * AST + c];
            vd[0] = vv.x; vd[1] = vv.y; vd[2] = vv.z; vd[3] = vv.w;
        }
        __syncthreads();

        float s[4][4];
        #pragma unroll
        for (int i = 0; i < 4; i++)
            #pragma unroll
            for (int j = 0; j < 4; j++) s[i][j] = 0.f;

        #pragma unroll 8
        for (int d = 0; d < 64; d++) {
            float a[4], bb[4];
            #pragma unroll
            for (int i = 0; i < 4; i++) a[i]  = Qs[(ty * 4 + i) * AST + d];
            #pragma unroll
            for (int j = 0; j < 4; j++) bb[j] = KP[(tx * 4 + j) * AST + d];
            #pragma unroll
            for (int i = 0; i < 4; i++)
                #pragma unroll
                for (int j = 0; j < 4; j++)
                    s[i][j] = fmaf(a[i], bb[j], s[i][j]);
        }
        __syncthreads();

        #pragma unroll
        for (int i = 0; i < 4; i++) {
            float mx = fmaxf(fmaxf(s[i][0], s[i][1]), fmaxf(s[i][2], s[i][3]));
            #pragma unroll
            for (int off = 8; off; off >>= 1)
                mx = fmaxf(mx, __shfl_xor_sync(0xffffffffu, mx, off, 16));
            const float mn   = fmaxf(m_i[i], mx);
            const float corr = __expf(m_i[i] - mn);
            m_i[i] = mn;
            float sum = 0.f;
            #pragma unroll
            for (int j = 0; j < 4; j++) {
                float p = __expf(s[i][j] - mn);
                s[i][j] = p; sum += p;
            }
            #pragma unroll
            for (int off = 8; off; off >>= 1)
                sum += __shfl_xor_sync(0xffffffffu, sum, off, 16);
            l_i[i] = l_i[i] * corr + sum;
            #pragma unroll
            for (int j = 0; j < 4; j++) o[i][j] *= corr;
            #pragma unroll
            for (int j = 0; j < 4; j++)
                KP[(ty * 4 + i) * AST + tx * 4 + j] = s[i][j];
        }
        __syncthreads();

        #pragma unroll 8
        for (int kq = 0; kq < 64; kq++) {
            float a[4], bb[4];
            #pragma unroll
            for (int i = 0; i < 4; i++) a[i]  = KP[(ty * 4 + i) * AST + kq];
            #pragma unroll
            for (int j = 0; j < 4; j++) bb[j] = Vs[kq * AST + tx * 4 + j];
            #pragma unroll
            for (int i = 0; i < 4; i++)
                #pragma unroll
                for (int j = 0; j < 4; j++)
                    o[i][j] = fmaf(a[i], bb[j], o[i][j]);
        }
    }

    #pragma unroll
    for (int i = 0; i < 4; i++) {
        const float inv = 1.0f / l_i[i];
        float4 ov;
        ov.x = rna_tf32(o[i][0] * inv); ov.y = rna_tf32(o[i][1] * inv);
        ov.z = rna_tf32(o[i][2] * inv); ov.w = rna_tf32(o[i][3] * inv);
        *(float4*)(Og + base + (size_t)(q0 + ty * 4 + i) * DD + tx * 4) = ov;
    }
}

// ---------------- launch -----------------------------------------------------
extern "C" void kernel_launch(void* const* d_in, const int* in_sizes, int n_in,
                              void* d_out, int out_size)
{
    const float* X   = (const float*)d_in[0];
    const float* Wq  = (const float*)d_in[1];
    const float* Wk  = (const float*)d_in[2];
    const float* Wv  = (const float*)d_in[3];
    const float* Wo  = (const float*)d_in[4];
    const float* W1  = (const float*)d_in[5];
    const float* b1  = (const float*)d_in[6];
    const float* W2  = (const float*)d_in[7];
    const float* b2  = (const float*)d_in[8];
    const float* g1  = (const float*)d_in[9];
    const float* be1 = (const float*)d_in[10];
    const float* g2  = (const float*)d_in[11];
    const float* be2 = (const float*)d_in[12];
    float* out = (float*)d_out;

    float *nX, *q, *k, *v, *ctx, *X1, *hbuf;
    float *WqT, *WkT, *WvT, *WoT, *W1T, *W2T;
    cudaGetSymbolAddress((void**)&nX,   g_nX);
    cudaGetSymbolAddress((void**)&q,    g_q);
    cudaGetSymbolAddress((void**)&k,    g_k);
    cudaGetSymbolAddress((void**)&v,    g_v);
    cudaGetSymbolAddress((void**)&ctx,  g_ctx);
    cudaGetSymbolAddress((void**)&X1,   g_X1);
    cudaGetSymbolAddress((void**)&hbuf, g_h);
    cudaGetSymbolAddress((void**)&WqT,  g_WqT);
    cudaGetSymbolAddress((void**)&WkT,  g_WkT);
    cudaGetSymbolAddress((void**)&WvT,  g_WvT);
    cudaGetSymbolAddress((void**)&WoT,  g_WoT);
    cudaGetSymbolAddress((void**)&W1T,  g_W1T);
    cudaGetSymbolAddress((void**)&W2T,  g_W2T);

    cudaFuncSetAttribute(tc_gemm, cudaFuncAttributeMaxDynamicSharedMemorySize,
                         TC_SMEM);
    cudaFuncSetAttribute(attn_kernel, cudaFuncAttributeMaxDynamicSharedMemorySize,
                         (int)(3 * 64 * AST * sizeof(float)));

    dim3 thr(256);

    // weight transposes (rna-rounded to tf32)
    transpose_rna_kernel<<<dim3(DD/32, DD/32), thr>>>(Wq, WqT, DD, DD);
    transpose_rna_kernel<<<dim3(DD/32, DD/32), thr>>>(Wk, WkT, DD, DD);
    transpose_rna_kernel<<<dim3(DD/32, DD/32), thr>>>(Wv, WvT, DD, DD);
    transpose_rna_kernel<<<dim3(DD/32, DD/32), thr>>>(Wo, WoT, DD, DD);
    transpose_rna_kernel<<<dim3(FF/32, DD/32), thr>>>(W1, W1T, DD, FF);
    transpose_rna_kernel<<<dim3(DD/32, FF/32), thr>>>(W2, W2T, FF, DD);

    // LN1
    ln_kernel<<<MR, thr>>>(X, g1, be1, nX);

    // QKV projections (tf32 tensor)
    dim3 gD(DD / 128, MR / 128);
    tc_gemm<<<gD, thr, TC_SMEM>>>(nX, WqT, q, MR, DD, DD, nullptr, nullptr, 0);
    tc_gemm<<<gD, thr, TC_SMEM>>>(nX, WkT, k, MR, DD, DD, nullptr, nullptr, 0);
    tc_gemm<<<gD, thr, TC_SMEM>>>(nX, WvT, v, MR, DD, DD, nullptr, nullptr, 0);

    // attention
    const size_t attn_smem = (size_t)3 * 64 * AST * sizeof(float);
    attn_kernel<<<dim3(SS / 64, BB * HH), thr, attn_smem>>>(q, k, v, ctx);

    // output projection + residual
    tc_gemm<<<gD, thr, TC_SMEM>>>(ctx, WoT, X1, MR, DD, DD, nullptr, X, 2);

    // LN2
    ln_kernel<<<MR, thr>>>(X1, g2, be2, nX);

    // FFN up: h = rna(relu(nX @ W1 + b1))
    tc_gemm<<<dim3(FF / 128, MR / 128), thr, TC_SMEM>>>(nX, W1T, hbuf,
                                                        MR, FF, DD, b1, nullptr,
                                                        1 | 4 | 8);

    // FFN down + residual: out = X1 + h @ W2 + b2
    tc_gemm<<<dim3(DD / 128, MR / 128), thr, TC_SMEM>>>(hbuf, W2T, out,
                                                        MR, DD, FF, b2, X1,
                                                        1 | 2);
}

// round 4
// speedup vs baseline: 3.2527x; 1.6794x over previous
#include <cuda_runtime.h>
#include <cuda_bf16.h>
#include <math_constants.h>
#include <cstdint>

// Problem constants
#define BB 2
#define SS 2048
#define DD 1024
#define HH 16
#define DK 64
#define FF 4096
#define MR (BB*SS)          // 4096 rows

// ---------------- scratch (static device globals: alloc-free rule) ----------
__device__ float g_nX [MR*DD];
__device__ float g_q  [MR*DD];
__device__ float g_k  [MR*DD];
__device__ float g_v  [MR*DD];
__device__ float g_ctx[MR*DD];
__device__ float g_X1 [MR*DD];
__device__ float g_h  [(size_t)MR*FF];
__device__ float g_WqT[DD*DD];
__device__ float g_WkT[DD*DD];
__device__ float g_WvT[DD*DD];
__device__ float g_WoT[DD*DD];
__device__ float g_W1T[(size_t)DD*FF];
__device__ float g_W2T[(size_t)DD*FF];

// ---------------- small helpers ---------------------------------------------
__device__ __forceinline__ uint32_t smem_u32(const void* p) {
    uint32_t a;
    asm("{ .reg .u64 t; cvta.to.shared.u64 t, %1; cvt.u32.u64 %0, t; }"
        : "=r"(a) : "l"(p));
    return a;
}
__device__ __forceinline__ float rna_tf32(float x) {
    uint32_t u;
    asm("cvt.rna.tf32.f32 %0, %1;" : "=r"(u) : "f"(x));
    return __uint_as_float(u);
}
__device__ __forceinline__ void cp16(uint32_t s, const void* g) {
    asm volatile("cp.async.cg.shared.global [%0], [%1], 16;" :: "r"(s), "l"(g));
}
__device__ __forceinline__ void mma_tf32(float* c, const uint32_t* a,
                                         const uint32_t* b) {
    asm volatile(
        "mma.sync.aligned.m16n8k8.row.col.f32.tf32.tf32.f32 "
        "{%0,%1,%2,%3}, {%4,%5,%6,%7}, {%8,%9}, {%0,%1,%2,%3};"
        : "+f"(c[0]), "+f"(c[1]), "+f"(c[2]), "+f"(c[3])
        : "r"(a[0]), "r"(a[1]), "r"(a[2]), "r"(a[3]),
          "r"(b[0]), "r"(b[1]));
}

// ---------------- weight transpose with tf32 round-to-nearest ---------------
__global__ __launch_bounds__(256)
void transpose_rna_kernel(const float* __restrict__ in, float* __restrict__ out,
                          int R, int C)
{
    __shared__ float t[32][33];
    const int bx = blockIdx.x * 32, by = blockIdx.y * 32;
    const int tx = threadIdx.x & 31, ty = threadIdx.x >> 5;  // 32 x 8
    #pragma unroll
    for (int i = 0; i < 32; i += 8)
        t[ty + i][tx] = in[(size_t)(by + ty + i) * C + bx + tx];
    __syncthreads();
    #pragma unroll
    for (int i = 0; i < 32; i += 8)
        out[(size_t)(bx + ty + i) * R + by + tx] = rna_tf32(t[tx][ty + i]);
}

// ---------------- LayerNorm (rna-rounded output) -----------------------------
__global__ __launch_bounds__(256)
void ln_kernel(const float* __restrict__ X, const float* __restrict__ g,
               const float* __restrict__ b, float* __restrict__ Y)
{
    const int row = blockIdx.x;
    const int tid = threadIdx.x;
    const float4 x = ((const float4*)(X + (size_t)row * DD))[tid];

    float s  = x.x + x.y + x.z + x.w;
    float ss = x.x*x.x + x.y*x.y + x.z*x.z + x.w*x.w;
    #pragma unroll
    for (int o = 16; o; o >>= 1) {
        s  += __shfl_xor_sync(0xffffffffu, s,  o);
        ss += __shfl_xor_sync(0xffffffffu, ss, o);
    }
    __shared__ float sw[8], sw2[8];
    const int w = tid >> 5, ln = tid & 31;
    if (ln == 0) { sw[w] = s; sw2[w] = ss; }
    __syncthreads();
    float tot = 0.f, tot2 = 0.f;
    #pragma unroll
    for (int i = 0; i < 8; i++) { tot += sw[i]; tot2 += sw2[i]; }

    const float mean = tot * (1.0f / DD);
    const float var  = tot2 * (1.0f / DD) - mean * mean;
    const float rstd = rsqrtf(var + 1e-5f);

    const float4 gv = ((const float4*)g)[tid];
    const float4 bv = ((const float4*)b)[tid];
    float4 y;
    y.x = rna_tf32((x.x - mean) * rstd * gv.x + bv.x);
    y.y = rna_tf32((x.y - mean) * rstd * gv.y + bv.y);
    y.z = rna_tf32((x.z - mean) * rstd * gv.z + bv.z);
    y.w = rna_tf32((x.w - mean) * rstd * gv.w + bv.w);
    ((float4*)(Y + (size_t)row * DD))[tid] = y;
}

// ---------------- tf32 mma.sync GEMM -----------------------------------------
// C[M,N] = A[M,K] @ Bt[N,K]^T.  mode: 1=+bias, 2=+resid, 4=relu, 8=rna out
#define KSTR 36
#define TILE_F (128 * KSTR)
#define STAGE_F (2 * TILE_F)
#define TC_SMEM (2 * STAGE_F * 4)           // 73728 bytes

__global__ __launch_bounds__(256, 2)
void tc_gemm(const float* __restrict__ A, const float* __restrict__ Bt,
             float* __restrict__ C, int M, int N, int K,
             const float* __restrict__ bias, const float* __restrict__ resid,
             int mode)
{
    extern __shared__ float smf[];
    const uint32_t sb = smem_u32(smf);

    const int tid  = threadIdx.x;
    const int wid  = tid >> 5, lane = tid & 31;
    const int tq   = lane >> 2, tr = lane & 3;
    const int wm   = (wid & 3) * 32;
    const int wn   = (wid >> 2) * 64;
    const int m0   = blockIdx.y * 128;
    const int n0   = blockIdx.x * 128;

    const int nk = K / 32;

    float acc[2][8][4];
    #pragma unroll
    for (int mt = 0; mt < 2; mt++)
        #pragma unroll
        for (int nt = 0; nt < 8; nt++)
            #pragma unroll
            for (int i = 0; i < 4; i++) acc[mt][nt][i] = 0.f;

    {
        const uint32_t sA = sb, sB = sb + TILE_F * 4;
        #pragma unroll
        for (int l = 0; l < 4; l++) {
            const int idx = tid + l * 256;
            const int r = idx >> 3, c = idx & 7;
            cp16(sA + (uint32_t)(r * KSTR + c * 4) * 4,
                 A + (size_t)(m0 + r) * K + c * 4);
            cp16(sB + (uint32_t)(r * KSTR + c * 4) * 4,
                 Bt + (size_t)(n0 + r) * K + c * 4);
        }
        asm volatile("cp.async.commit_group;" ::: "memory");
    }

    for (int kt = 0; kt < nk; kt++) {
        if (kt + 1 < nk) {
            const int s = (kt + 1) & 1;
            const uint32_t sA = sb + (uint32_t)s * STAGE_F * 4;
            const uint32_t sB = sA + TILE_F * 4;
            const int kof = (kt + 1) * 32;
            #pragma unroll
            for (int l = 0; l < 4; l++) {
                const int idx = tid + l * 256;
                const int r = idx >> 3, c = idx & 7;
                cp16(sA + (uint32_t)(r * KSTR + c * 4) * 4,
                     A + (size_t)(m0 + r) * K + kof + c * 4);
                cp16(sB + (uint32_t)(r * KSTR + c * 4) * 4,
                     Bt + (size_t)(n0 + r) * K + kof + c * 4);
            }
            asm volatile("cp.async.commit_group;" ::: "memory");
            asm volatile("cp.async.wait_group 1;" ::: "memory");
        } else {
            asm volatile("cp.async.wait_group 0;" ::: "memory");
        }
        __syncthreads();

        const uint32_t* Asu = (const uint32_t*)(smf + (size_t)(kt & 1) * STAGE_F);
        const uint32_t* Bsu = Asu + TILE_F;

        #pragma unroll
        for (int ks = 0; ks < 4; ks++) {
            const int kc = ks * 8 + tr;
            uint32_t a[2][4], b[8][2];
            #pragma unroll
            for (int mt = 0; mt < 2; mt++) {
                const int row = wm + mt * 16 + tq;
                a[mt][0] = Asu[row * KSTR + kc];
                a[mt][1] = Asu[(row + 8) * KSTR + kc];
                a[mt][2] = Asu[row * KSTR + kc + 4];
                a[mt][3] = Asu[(row + 8) * KSTR + kc + 4];
            }
            #pragma unroll
            for (int nt = 0; nt < 8; nt++) {
                const int col = wn + nt * 8 + tq;
                b[nt][0] = Bsu[col * KSTR + kc];
                b[nt][1] = Bsu[col * KSTR + kc + 4];
            }
            #pragma unroll
            for (int mt = 0; mt < 2; mt++)
                #pragma unroll
                for (int nt = 0; nt < 8; nt++)
                    mma_tf32(acc[mt][nt], a[mt], b[nt]);
        }
        __syncthreads();
    }

    #pragma unroll
    for (int mt = 0; mt < 2; mt++) {
        const int r0 = m0 + wm + mt * 16 + tq;
        #pragma unroll
        for (int half = 0; half < 2; half++) {
            const int m = r0 + half * 8;
            #pragma unroll
            for (int nt = 0; nt < 8; nt++) {
                const int n = n0 + wn + nt * 8 + tr * 2;
                float vx = acc[mt][nt][half * 2 + 0];
                float vy = acc[mt][nt][half * 2 + 1];
                if (mode & 1) {
                    const float2 bb = *(const float2*)(bias + n);
                    vx += bb.x; vy += bb.y;
                }
                if (mode & 2) {
                    const float2 rr = *(const float2*)(resid + (size_t)m * N + n);
                    vx += rr.x; vy += rr.y;
                }
                if (mode & 4) { vx = fmaxf(vx, 0.f); vy = fmaxf(vy, 0.f); }
                if (mode & 8) { vx = rna_tf32(vx); vy = rna_tf32(vy); }
                float2 o; o.x = vx; o.y = vy;
                *(float2*)(C + (size_t)m * N + n) = o;
            }
        }
    }
}

// ---------------- Flash attention on tensor cores (tf32 mma) ------------------
// 8 warps, 128 q-rows per CTA; k tiles of 64. Warp owns 16 q-rows.
// Strides: Q/K/P = 68 floats (conflict-free a/b frags), V = 72 (conflict-free b).
#define ASQ 68
#define ASV 72
#define ATT_SMEM ((128*ASQ + 64*ASQ + 64*ASV + 128*ASQ) * 4)   // 105472 B

__global__ __launch_bounds__(256, 2)
void attn_mma_kernel(const float* __restrict__ Qg, const float* __restrict__ Kg,
                     const float* __restrict__ Vg, float* __restrict__ Og)
{
    extern __shared__ float sm[];
    float* Qs = sm;                       // [128][68]
    float* Ks = sm + 128 * ASQ;           // [64][68]   (n=seq_k, k=d)
    float* Vs = Ks + 64 * ASQ;            // [64][72]   (k=seq_k rows, n=d cols)
    float* Ps = Vs + 64 * ASV;            // [128][68]  (warp-private 16-row slabs)

    const int tid  = threadIdx.x;
    const int wid  = tid >> 5, lane = tid & 31;
    const int tq   = lane >> 2, tr = lane & 3;
    const int wq0  = wid * 16;
    const int bh   = blockIdx.y;
    const int b    = bh >> 4, h = bh & 15;
    const size_t base = (size_t)b * SS * DD + (size_t)h * DK;
    const int q0   = blockIdx.x * 128;

    // load Q tile: 128x64, scaled 1/8, rna to tf32
    #pragma unroll
    for (int l = 0; l < 8; l++) {
        const int idx = tid + l * 256;
        const int r = idx >> 4, c = (idx & 15) << 2;
        float4 qv = *(const float4*)(Qg + base + (size_t)(q0 + r) * DD + c);
        float4 w;
        w.x = rna_tf32(qv.x * 0.125f); w.y = rna_tf32(qv.y * 0.125f);
        w.z = rna_tf32(qv.z * 0.125f); w.w = rna_tf32(qv.w * 0.125f);
        *(float4*)(Qs + r * ASQ + c) = w;
    }

    float m_[2], l_[2], o[8][4];
    m_[0] = m_[1] = -CUDART_INF_F;
    l_[0] = l_[1] = 0.f;
    #pragma unroll
    for (int nt = 0; nt < 8; nt++)
        #pragma unroll
        for (int i = 0; i < 4; i++) o[nt][i] = 0.f;

    const uint32_t* Qu = (const uint32_t*)Qs;
    const uint32_t* Ku = (const uint32_t*)Ks;
    const uint32_t* Vu = (const uint32_t*)Vs;
    const uint32_t* Pu = (const uint32_t*)Ps;

    for (int kt = 0; kt < SS / 64; kt++) {
        __syncthreads();                       // prior PV done with Ks/Vs
        const int kb = kt * 64;
        #pragma unroll
        for (int l = 0; l < 4; l++) {
            const int idx = tid + l * 256;
            const int r = idx >> 4, c = (idx & 15) << 2;
            float4 kv = *(const float4*)(Kg + base + (size_t)(kb + r) * DD + c);
            float4 wk;
            wk.x = rna_tf32(kv.x); wk.y = rna_tf32(kv.y);
            wk.z = rna_tf32(kv.z); wk.w = rna_tf32(kv.w);
            *(float4*)(Ks + r * ASQ + c) = wk;
            float4 vv = *(const float4*)(Vg + base + (size_t)(kb + r) * DD + c);
            float4 wv;
            wv.x = rna_tf32(vv.x); wv.y = rna_tf32(vv.y);
            wv.z = rna_tf32(vv.z); wv.w = rna_tf32(vv.w);
            *(float4*)(Vs + r * ASV + c) = wv;
        }
        __syncthreads();

        // S = Q @ K^T  (m16 x n64 x k64 per warp)
        float s[8][4];
        #pragma unroll
        for (int nt = 0; nt < 8; nt++)
            #pragma unroll
            for (int i = 0; i < 4; i++) s[nt][i] = 0.f;

        #pragma unroll
        for (int ks = 0; ks < 8; ks++) {
            const int kc = ks * 8 + tr;
            uint32_t a[4];
            a[0] = Qu[(wq0 + tq) * ASQ + kc];
            a[1] = Qu[(wq0 + tq + 8) * ASQ + kc];
            a[2] = Qu[(wq0 + tq) * ASQ + kc + 4];
            a[3] = Qu[(wq0 + tq + 8) * ASQ + kc + 4];
            #pragma unroll
            for (int nt = 0; nt < 8; nt++) {
                uint32_t bb[2];
                bb[0] = Ku[(nt * 8 + tq) * ASQ + kc];
                bb[1] = Ku[(nt * 8 + tq) * ASQ + kc + 4];
                mma_tf32(s[nt], a, bb);
            }
        }

        // online softmax in fragment layout (rows tq and tq+8)
        #pragma unroll
        for (int half = 0; half < 2; half++) {
            float mx = -CUDART_INF_F;
            #pragma unroll
            for (int nt = 0; nt < 8; nt++)
                mx = fmaxf(mx, fmaxf(s[nt][half * 2], s[nt][half * 2 + 1]));
            mx = fmaxf(mx, __shfl_xor_sync(0xffffffffu, mx, 1));
            mx = fmaxf(mx, __shfl_xor_sync(0xffffffffu, mx, 2));
            const float mn   = fmaxf(m_[half], mx);
            const float corr = __expf(m_[half] - mn);
            m_[half] = mn;
            float sum = 0.f;
            #pragma unroll
            for (int nt = 0; nt < 8; nt++) {
                float p0 = __expf(s[nt][half * 2]     - mn);
                float p1 = __expf(s[nt][half * 2 + 1] - mn);
                s[nt][half * 2]     = p0;
                s[nt][half * 2 + 1] = p1;
                sum += p0 + p1;
            }
            sum += __shfl_xor_sync(0xffffffffu, sum, 1);
            sum += __shfl_xor_sync(0xffffffffu, sum, 2);
            l_[half] = l_[half] * corr + sum;
            #pragma unroll
            for (int nt = 0; nt < 8; nt++) {
                o[nt][half * 2]     *= corr;
                o[nt][half * 2 + 1] *= corr;
            }
        }

        // store P slab (warp-private rows), rna to tf32
        #pragma unroll
        for (int nt = 0; nt < 8; nt++) {
            const int col = nt * 8 + tr * 2;
            float2 p0, p1;
            p0.x = rna_tf32(s[nt][0]); p0.y = rna_tf32(s[nt][1]);
            p1.x = rna_tf32(s[nt][2]); p1.y = rna_tf32(s[nt][3]);
            *(float2*)(Ps + (wq0 + tq) * ASQ + col)     = p0;
            *(float2*)(Ps + (wq0 + tq + 8) * ASQ + col) = p1;
        }
        __syncwarp();

        // O += P @ V  (m16 x n64(d) x k64(seq))
        #pragma unroll
        for (int ks = 0; ks < 8; ks++) {
            const int kc = ks * 8 + tr;
            uint32_t a[4];
            a[0] = Pu[(wq0 + tq) * ASQ + kc];
            a[1] = Pu[(wq0 + tq + 8) * ASQ + kc];
            a[2] = Pu[(wq0 + tq) * ASQ + kc + 4];
            a[3] = Pu[(wq0 + tq + 8) * ASQ + kc + 4];
            #pragma unroll
            for (int nt = 0; nt < 8; nt++) {
                uint32_t bb[2];
                bb[0] = Vu[kc * ASV + nt * 8 + tq];
                bb[1] = Vu[(kc + 4) * ASV + nt * 8 + tq];
                mma_tf32(o[nt], a, bb);
            }
        }
    }

    // normalize + store ctx (rna for downstream tf32 GEMM)
    const float inv0 = 1.0f / l_[0];
    const float inv1 = 1.0f / l_[1];
    #pragma unroll
    for (int nt = 0; nt < 8; nt++) {
        const int col = nt * 8 + tr * 2;
        float2 o0, o1;
        o0.x = rna_tf32(o[nt][0] * inv0); o0.y = rna_tf32(o[nt][1] * inv0);
        o1.x = rna_tf32(o[nt][2] * inv1); o1.y = rna_tf32(o[nt][3] * inv1);
        *(float2*)(Og + base + (size_t)(q0 + wq0 + tq) * DD + col)     = o0;
        *(float2*)(Og + base + (size_t)(q0 + wq0 + tq + 8) * DD + col) = o1;
    }
}

// ---------------- launch -----------------------------------------------------
extern "C" void kernel_launch(void* const* d_in, const int* in_sizes, int n_in,
                              void* d_out, int out_size)
{
    const float* X   = (const float*)d_in[0];
    const float* Wq  = (const float*)d_in[1];
    const float* Wk  = (const float*)d_in[2];
    const float* Wv  = (const float*)d_in[3];
    const float* Wo  = (const float*)d_in[4];
    const float* W1  = (const float*)d_in[5];
    const float* b1  = (const float*)d_in[6];
    const float* W2  = (const float*)d_in[7];
    const float* b2  = (const float*)d_in[8];
    const float* g1  = (const float*)d_in[9];
    const float* be1 = (const float*)d_in[10];
    const float* g2  = (const float*)d_in[11];
    const float* be2 = (const float*)d_in[12];
    float* out = (float*)d_out;

    float *nX, *q, *k, *v, *ctx, *X1, *hbuf;
    float *WqT, *WkT, *WvT, *WoT, *W1T, *W2T;
    cudaGetSymbolAddress((void**)&nX,   g_nX);
    cudaGetSymbolAddress((void**)&q,    g_q);
    cudaGetSymbolAddress((void**)&k,    g_k);
    cudaGetSymbolAddress((void**)&v,    g_v);
    cudaGetSymbolAddress((void**)&ctx,  g_ctx);
    cudaGetSymbolAddress((void**)&X1,   g_X1);
    cudaGetSymbolAddress((void**)&hbuf, g_h);
    cudaGetSymbolAddress((void**)&WqT,  g_WqT);
    cudaGetSymbolAddress((void**)&WkT,  g_WkT);
    cudaGetSymbolAddress((void**)&WvT,  g_WvT);
    cudaGetSymbolAddress((void**)&WoT,  g_WoT);
    cudaGetSymbolAddress((void**)&W1T,  g_W1T);
    cudaGetSymbolAddress((void**)&W2T,  g_W2T);

    cudaFuncSetAttribute(tc_gemm, cudaFuncAttributeMaxDynamicSharedMemorySize,
                         TC_SMEM);
    cudaFuncSetAttribute(attn_mma_kernel,
                         cudaFuncAttributeMaxDynamicSharedMemorySize, ATT_SMEM);

    dim3 thr(256);

    // weight transposes (rna-rounded to tf32)
    transpose_rna_kernel<<<dim3(DD/32, DD/32), thr>>>(Wq, WqT, DD, DD);
    transpose_rna_kernel<<<dim3(DD/32, DD/32), thr>>>(Wk, WkT, DD, DD);
    transpose_rna_kernel<<<dim3(DD/32, DD/32), thr>>>(Wv, WvT, DD, DD);
    transpose_rna_kernel<<<dim3(DD/32, DD/32), thr>>>(Wo, WoT, DD, DD);
    transpose_rna_kernel<<<dim3(FF/32, DD/32), thr>>>(W1, W1T, DD, FF);
    transpose_rna_kernel<<<dim3(DD/32, FF/32), thr>>>(W2, W2T, FF, DD);

    // LN1
    ln_kernel<<<MR, thr>>>(X, g1, be1, nX);

    // QKV projections (tf32 tensor)
    dim3 gD(DD / 128, MR / 128);
    tc_gemm<<<gD, thr, TC_SMEM>>>(nX, WqT, q, MR, DD, DD, nullptr, nullptr, 0);
    tc_gemm<<<gD, thr, TC_SMEM>>>(nX, WkT, k, MR, DD, DD, nullptr, nullptr, 0);
    tc_gemm<<<gD, thr, TC_SMEM>>>(nX, WvT, v, MR, DD, DD, nullptr, nullptr, 0);

    // attention (tensor-core flash)
    attn_mma_kernel<<<dim3(SS / 128, BB * HH), thr, ATT_SMEM>>>(q, k, v, ctx);

    // output projection + residual
    tc_gemm<<<gD, thr, TC_SMEM>>>(ctx, WoT, X1, MR, DD, DD, nullptr, X, 2);

    // LN2
    ln_kernel<<<MR, thr>>>(X1, g2, be2, nX);

    // FFN up: h = rna(relu(nX @ W1 + b1))
    tc_gemm<<<dim3(FF / 128, MR / 128), thr, TC_SMEM>>>(nX, W1T, hbuf,
                                                        MR, FF, DD, b1, nullptr,
                                                        1 | 4 | 8);

    // FFN down + residual: out = X1 + h @ W2 + b2
    tc_gemm<<<dim3(DD / 128, MR / 128), thr, TC_SMEM>>>(hbuf, W2T, out,
                                                        MR, DD, FF, b2, X1,
                                                        1 | 2);
}